// round 8
// baseline (speedup 1.0000x reference)
#include <cuda_runtime.h>
#include <cuda_bf16.h>
#include <math.h>
#include <stdint.h>

// ---------------------------------------------------------------------------
// GCN_47760036331636: 2-layer GCN.
//   Layer1 GEMM via mma.sync bf16-split (xhi@Whi + xhi@Wlo + xlo@Whi, fp32 acc)
//   CSR-gather aggregation (unrolled x4 for MLP), SIMT cp.async GEMM2.
// ---------------------------------------------------------------------------

#define NODES  50000
#define EDGES  800000
#define IN_C   512
#define HID_C  256
#define OUT_C  64

// Scratch (allocation-free: __device__ globals)
__device__ int   g_is64;
__device__ int   g_src [EDGES];
__device__ int   g_dst [EDGES];
__device__ int   g_cnt [NODES];
__device__ int   g_cur [NODES];
__device__ int   g_rs  [NODES + 1];
__device__ int   g_psrc[EDGES];
__device__ float g_pw  [EDGES];
__device__ float g_dinv[NODES];
__device__ __nv_bfloat16 g_xhi [(size_t)NODES * IN_C];
__device__ __nv_bfloat16 g_xlo [(size_t)NODES * IN_C];
__device__ __nv_bfloat16 g_wthi[(size_t)HID_C * IN_C];   // W1^T, [n][k]
__device__ __nv_bfloat16 g_wtlo[(size_t)HID_C * IN_C];
__device__ float g_h1  [(size_t)NODES * HID_C];
__device__ float g_out1[(size_t)NODES * HID_C];
__device__ float g_h2  [(size_t)NODES * OUT_C];

#define CP_ASYNC16(dst32, srcp, pbytes) \
    asm volatile("cp.async.cg.shared.global [%0], [%1], 16, %2;" \
                 :: "r"(dst32), "l"(srcp), "r"(pbytes) : "memory")
#define CP_COMMIT()  asm volatile("cp.async.commit_group;" ::: "memory")
#define CP_WAIT(N)   asm volatile("cp.async.wait_group %0;" :: "n"(N) : "memory")

// ---------------------------------------------------------------------------
// Parallel edge-dtype detection: 1024 threads, one 8B probe each.
// int64 data => every probe < n; int32 data read as u64 => huge values.
// ---------------------------------------------------------------------------
__global__ void k_detect(const void* ei, int E, int n) {
    int cnt = E < 1024 ? E : 1024;
    int bad = 0;
    if ((int)threadIdx.x < cnt) {
        unsigned long long v = ((const unsigned long long*)ei)[threadIdx.x];
        bad = (v >= (unsigned long long)n);
    }
    bad = __syncthreads_or(bad);
    if (threadIdx.x == 0) g_is64 = !bad;
}

// Fused edge conversion + degree count (cnt/cur pre-zeroed)
__global__ void k_convert_count(const void* ei, int E, int* cnt) {
    int e = blockIdx.x * blockDim.x + threadIdx.x;
    if (e >= E) return;
    int s, d;
    if (g_is64) {
        const long long* p = (const long long*)ei;
        s = (int)p[e]; d = (int)p[E + e];
    } else {
        const int* p = (const int*)ei;
        s = p[e]; d = p[E + e];
    }
    g_src[e] = s;
    g_dst[e] = d;
    atomicAdd(cnt + d, 1);
}

// ---------------------------------------------------------------------------
// CSR build: zero -> (convert+count) -> dinv -> scan -> fill
// ---------------------------------------------------------------------------
__global__ void k_zero2(int* a, int* b, int n) {
    int i = blockIdx.x * blockDim.x + threadIdx.x;
    if (i < n) { a[i] = 0; b[i] = 0; }
}

__global__ void k_dinv(const int* __restrict__ cnt, float* __restrict__ dinv, int n) {
    int i = blockIdx.x * blockDim.x + threadIdx.x;
    if (i < n) dinv[i] = rsqrtf(1.0f + (float)cnt[i]);
}

__global__ void k_scan(const int* __restrict__ cnt, int* __restrict__ rs, int n) {
    __shared__ int wsum[32];
    __shared__ int carry;
    int tid = threadIdx.x, lane = tid & 31, wid = tid >> 5;
    if (tid == 0) carry = 0;
    __syncthreads();
    for (int base = 0; base < n; base += 1024) {
        int idx = base + tid;
        int v = (idx < n) ? cnt[idx] : 0;
        int x = v;
        #pragma unroll
        for (int o = 1; o < 32; o <<= 1) {
            int t = __shfl_up_sync(0xFFFFFFFFu, x, o);
            if (lane >= o) x += t;
        }
        if (lane == 31) wsum[wid] = x;
        __syncthreads();
        if (wid == 0) {
            int y = wsum[lane];
            #pragma unroll
            for (int o = 1; o < 32; o <<= 1) {
                int t = __shfl_up_sync(0xFFFFFFFFu, y, o);
                if (lane >= o) y += t;
            }
            wsum[lane] = y;
        }
        __syncthreads();
        int excl = carry + x - v + (wid ? wsum[wid - 1] : 0);
        if (idx < n) rs[idx] = excl;
        int total = wsum[31];
        __syncthreads();
        if (tid == 0) carry += total;
        __syncthreads();
    }
    if (tid == 0) rs[n] = carry;
}

__global__ void k_fill(const int* __restrict__ src, const int* __restrict__ dst,
                       const int* __restrict__ rs, int* __restrict__ cur,
                       const float* __restrict__ dinv,
                       int* __restrict__ psrc, float* __restrict__ pw, int E)
{
    int e = blockIdx.x * blockDim.x + threadIdx.x;
    if (e >= E) return;
    int s = src[e], d = dst[e];
    int pos = rs[d] + atomicAdd(cur + d, 1);
    psrc[pos] = s;
    pw[pos]   = dinv[s] * dinv[d];
}

// ---------------------------------------------------------------------------
// bf16 hi/lo split of x; transpose+split of W1
// ---------------------------------------------------------------------------
__global__ void k_split_x(const float* __restrict__ x, __nv_bfloat16* __restrict__ hi,
                          __nv_bfloat16* __restrict__ lo, int total4)
{
    int i = blockIdx.x * blockDim.x + threadIdx.x;
    if (i >= total4) return;
    float4 v = reinterpret_cast<const float4*>(x)[i];
    __nv_bfloat16 h0 = __float2bfloat16(v.x), h1 = __float2bfloat16(v.y);
    __nv_bfloat16 h2 = __float2bfloat16(v.z), h3 = __float2bfloat16(v.w);
    __nv_bfloat16 l0 = __float2bfloat16(v.x - __bfloat162float(h0));
    __nv_bfloat16 l1 = __float2bfloat16(v.y - __bfloat162float(h1));
    __nv_bfloat16 l2 = __float2bfloat16(v.z - __bfloat162float(h2));
    __nv_bfloat16 l3 = __float2bfloat16(v.w - __bfloat162float(h3));
    reinterpret_cast<__nv_bfloat162*>(hi)[i * 2 + 0] = __nv_bfloat162(h0, h1);
    reinterpret_cast<__nv_bfloat162*>(hi)[i * 2 + 1] = __nv_bfloat162(h2, h3);
    reinterpret_cast<__nv_bfloat162*>(lo)[i * 2 + 0] = __nv_bfloat162(l0, l1);
    reinterpret_cast<__nv_bfloat162*>(lo)[i * 2 + 1] = __nv_bfloat162(l2, l3);
}

__global__ void k_split_wt(const float* __restrict__ W, __nv_bfloat16* __restrict__ hi,
                           __nv_bfloat16* __restrict__ lo)
{
    int idx = blockIdx.x * blockDim.x + threadIdx.x;
    if (idx >= HID_C * IN_C) return;
    int k = idx / HID_C, n = idx % HID_C;
    float v = W[idx];
    __nv_bfloat16 h = __float2bfloat16(v);
    hi[(size_t)n * IN_C + k] = h;
    lo[(size_t)n * IN_C + k] = __float2bfloat16(v - __bfloat162float(h));
}

// ---------------------------------------------------------------------------
// mma.sync bf16-split GEMM1 (unchanged from R7; it works)
// ---------------------------------------------------------------------------
#define G1_BK     32
#define G1_SA     40
#define G1_TILE   (128 * G1_SA)
#define G1_SMEM   (8 * G1_TILE * 2)       // 81920 bytes

__device__ __forceinline__ uint32_t ld2h(const __nv_bfloat16* base, int row, int col) {
    return *reinterpret_cast<const uint32_t*>(base + row * G1_SA + col);
}
__device__ __forceinline__ void mma_bf16(float* d, const uint32_t* a, const uint32_t* b) {
    asm volatile(
        "mma.sync.aligned.m16n8k16.row.col.f32.bf16.bf16.f32 "
        "{%0,%1,%2,%3}, {%4,%5,%6,%7}, {%8,%9}, {%0,%1,%2,%3};"
        : "+f"(d[0]), "+f"(d[1]), "+f"(d[2]), "+f"(d[3])
        : "r"(a[0]), "r"(a[1]), "r"(a[2]), "r"(a[3]), "r"(b[0]), "r"(b[1]));
}

__global__ void __launch_bounds__(256) k_gemm1_mma(
    const __nv_bfloat16* __restrict__ xhi, const __nv_bfloat16* __restrict__ xlo,
    const __nv_bfloat16* __restrict__ wthi, const __nv_bfloat16* __restrict__ wtlo,
    float* __restrict__ C, int M)
{
    extern __shared__ __nv_bfloat16 sm[];
    __nv_bfloat16* AHI[2] = { sm,              sm + G1_TILE     };
    __nv_bfloat16* ALO[2] = { sm + 2*G1_TILE,  sm + 3*G1_TILE   };
    __nv_bfloat16* BHI[2] = { sm + 4*G1_TILE,  sm + 5*G1_TILE   };
    __nv_bfloat16* BLO[2] = { sm + 6*G1_TILE,  sm + 7*G1_TILE   };

    const int tid  = threadIdx.x;
    const int warp = tid >> 5, lane = tid & 31;
    const int qr = lane >> 2, qc = lane & 3;
    const int wm0 = (warp >> 2) * 64;
    const int wn0 = (warp & 3) * 32;
    const int mBase   = blockIdx.y * 128;
    const int colBase = blockIdx.x * 128;

    auto load_stage = [&](int buf, int k0) {
        #pragma unroll
        for (int l = 0; l < 2; l++) {
            int idx = tid + l * 256;
            int r = idx >> 2, ch = idx & 3;
            uint32_t soff = (uint32_t)((r * G1_SA + ch * 8) * 2);
            int gm  = mBase + r;
            int gmc = gm < M ? gm : M - 1;
            int p   = gm < M ? 16 : 0;
            const __nv_bfloat16* sa_hi = xhi + (size_t)gmc * IN_C + k0 + ch * 8;
            const __nv_bfloat16* sa_lo = xlo + (size_t)gmc * IN_C + k0 + ch * 8;
            CP_ASYNC16((uint32_t)__cvta_generic_to_shared(AHI[buf]) + soff, sa_hi, p);
            CP_ASYNC16((uint32_t)__cvta_generic_to_shared(ALO[buf]) + soff, sa_lo, p);
            const __nv_bfloat16* sb_hi = wthi + (size_t)(colBase + r) * IN_C + k0 + ch * 8;
            const __nv_bfloat16* sb_lo = wtlo + (size_t)(colBase + r) * IN_C + k0 + ch * 8;
            CP_ASYNC16((uint32_t)__cvta_generic_to_shared(BHI[buf]) + soff, sb_hi, 16);
            CP_ASYNC16((uint32_t)__cvta_generic_to_shared(BLO[buf]) + soff, sb_lo, 16);
        }
        CP_COMMIT();
    };

    float acc[4][4][4];
    #pragma unroll
    for (int i = 0; i < 4; i++)
        #pragma unroll
        for (int j = 0; j < 4; j++)
            #pragma unroll
            for (int r = 0; r < 4; r++) acc[i][j][r] = 0.0f;

    const int nk = IN_C / G1_BK;
    load_stage(0, 0);

    for (int kt = 0; kt < nk; kt++) {
        int buf = kt & 1;
        if (kt + 1 < nk) { load_stage(buf ^ 1, (kt + 1) * G1_BK); CP_WAIT(1); }
        else             { CP_WAIT(0); }
        __syncthreads();

        #pragma unroll
        for (int ks = 0; ks < 2; ks++) {
            const int kh = ks * 16;
            uint32_t ahi[4][4], alo[4][4], bhi[4][2], blo[4][2];
            #pragma unroll
            for (int i = 0; i < 4; i++) {
                int r0 = wm0 + i * 16 + qr;
                int c0 = kh + qc * 2;
                ahi[i][0] = ld2h(AHI[buf], r0,     c0);
                ahi[i][1] = ld2h(AHI[buf], r0 + 8, c0);
                ahi[i][2] = ld2h(AHI[buf], r0,     c0 + 8);
                ahi[i][3] = ld2h(AHI[buf], r0 + 8, c0 + 8);
                alo[i][0] = ld2h(ALO[buf], r0,     c0);
                alo[i][1] = ld2h(ALO[buf], r0 + 8, c0);
                alo[i][2] = ld2h(ALO[buf], r0,     c0 + 8);
                alo[i][3] = ld2h(ALO[buf], r0 + 8, c0 + 8);
            }
            #pragma unroll
            for (int j = 0; j < 4; j++) {
                int nr = wn0 + j * 8 + qr;
                int c0 = kh + qc * 2;
                bhi[j][0] = ld2h(BHI[buf], nr, c0);
                bhi[j][1] = ld2h(BHI[buf], nr, c0 + 8);
                blo[j][0] = ld2h(BLO[buf], nr, c0);
                blo[j][1] = ld2h(BLO[buf], nr, c0 + 8);
            }
            #pragma unroll
            for (int i = 0; i < 4; i++)
                #pragma unroll
                for (int j = 0; j < 4; j++) {
                    mma_bf16(acc[i][j], ahi[i], bhi[j]);
                    mma_bf16(acc[i][j], ahi[i], blo[j]);
                    mma_bf16(acc[i][j], alo[i], bhi[j]);
                }
        }
        __syncthreads();
    }

    #pragma unroll
    for (int i = 0; i < 4; i++) {
        int m0 = mBase + wm0 + i * 16 + qr;
        #pragma unroll
        for (int j = 0; j < 4; j++) {
            int nc = colBase + wn0 + j * 8 + qc * 2;
            if (m0 < M)
                *reinterpret_cast<float2*>(C + (size_t)m0 * HID_C + nc) =
                    make_float2(acc[i][j][0], acc[i][j][1]);
            if (m0 + 8 < M)
                *reinterpret_cast<float2*>(C + (size_t)(m0 + 8) * HID_C + nc) =
                    make_float2(acc[i][j][2], acc[i][j][3]);
        }
    }
}

// ---------------------------------------------------------------------------
// Double-buffered cp.async fp32 GEMM (layer 2)
// ---------------------------------------------------------------------------
template<int BM, int BN, int BK, int TM, int TN>
__global__ void k_gemm_db(const float* __restrict__ A, const float* __restrict__ B,
                          float* __restrict__ C, int M, int N, int K)
{
    constexpr int THREADS = (BM / TM) * (BN / TN);
    constexpr int APAD = 4;
    __shared__ float As[2][BM][BK + APAD];
    __shared__ float Bs[2][BK][BN];

    const int tid = threadIdx.x;
    const int tx  = tid % (BN / TN);
    const int ty  = tid / (BN / TN);
    const int rowBase = blockIdx.y * BM;
    const int colBase = blockIdx.x * BN;

    constexpr int NA = BM * BK / 4 / THREADS;
    constexpr int NB = BK * BN / 4 / THREADS;

    int a_ar[NA], a_ac[NA];
    #pragma unroll
    for (int l = 0; l < NA; l++) {
        int idx = tid + l * THREADS;
        a_ar[l] = idx / (BK / 4);
        a_ac[l] = (idx % (BK / 4)) * 4;
    }
    int b_br[NB], b_bc[NB];
    #pragma unroll
    for (int l = 0; l < NB; l++) {
        int idx = tid + l * THREADS;
        b_br[l] = idx / (BN / 4);
        b_bc[l] = (idx % (BN / 4)) * 4;
    }

    auto load_tiles = [&](int buf, int k0) {
        #pragma unroll
        for (int l = 0; l < NA; l++) {
            int gr = rowBase + a_ar[l];
            int grc = gr < M ? gr : M - 1;
            const float* src = A + (size_t)grc * K + k0 + a_ac[l];
            uint32_t d = (uint32_t)__cvta_generic_to_shared(&As[buf][a_ar[l]][a_ac[l]]);
            int p = gr < M ? 16 : 0;
            CP_ASYNC16(d, src, p);
        }
        #pragma unroll
        for (int l = 0; l < NB; l++) {
            const float* src = B + (size_t)(k0 + b_br[l]) * N + colBase + b_bc[l];
            uint32_t d = (uint32_t)__cvta_generic_to_shared(&Bs[buf][b_br[l]][b_bc[l]]);
            CP_ASYNC16(d, src, 16);
        }
        CP_COMMIT();
    };

    float acc[TM][TN];
    #pragma unroll
    for (int i = 0; i < TM; i++)
        #pragma unroll
        for (int j = 0; j < TN; j++) acc[i][j] = 0.0f;

    const int nk = K / BK;
    load_tiles(0, 0);

    for (int kt = 0; kt < nk; kt++) {
        int buf = kt & 1;
        if (kt + 1 < nk) { load_tiles(buf ^ 1, (kt + 1) * BK); CP_WAIT(1); }
        else             { CP_WAIT(0); }
        __syncthreads();

        #pragma unroll
        for (int kk = 0; kk < BK; kk++) {
            float a[TM], b[TN];
            #pragma unroll
            for (int i = 0; i < TM; i++) a[i] = As[buf][ty * TM + i][kk];
            #pragma unroll
            for (int j = 0; j < TN; j += 4) {
                float4 t = *reinterpret_cast<const float4*>(&Bs[buf][kk][tx * TN + j]);
                b[j] = t.x; b[j + 1] = t.y; b[j + 2] = t.z; b[j + 3] = t.w;
            }
            #pragma unroll
            for (int i = 0; i < TM; i++)
                #pragma unroll
                for (int j = 0; j < TN; j++)
                    acc[i][j] = fmaf(a[i], b[j], acc[i][j]);
        }
        __syncthreads();
    }

    #pragma unroll
    for (int i = 0; i < TM; i++) {
        int gr = rowBase + ty * TM + i;
        if (gr >= M) continue;
        #pragma unroll
        for (int j = 0; j < TN; j += 4) {
            float4 v = make_float4(acc[i][j], acc[i][j+1], acc[i][j+2], acc[i][j+3]);
            *reinterpret_cast<float4*>(&C[(size_t)gr * N + colBase + tx * TN + j]) = v;
        }
    }
}

// ---------------------------------------------------------------------------
// CSR aggregation, edge loop unrolled x4 (4 independent accumulators -> MLP=4)
// ---------------------------------------------------------------------------
template<int C, bool RELU>
__global__ void k_agg(const int* __restrict__ rs, const int* __restrict__ psrc,
                      const float* __restrict__ pw, const float* __restrict__ h,
                      const float* __restrict__ dinv, const float* __restrict__ bias,
                      float* __restrict__ out, int n)
{
    constexpr int TPN = C / 4;
    constexpr int NPB = 256 / TPN;
    int sub  = threadIdx.x / TPN;
    int t    = threadIdx.x % TPN;
    int node = blockIdx.x * NPB + sub;
    if (node >= n) return;

    const float4* h4 = reinterpret_cast<const float4*>(h);
    int beg = rs[node], end = rs[node + 1];

    float4 a0 = make_float4(0.f, 0.f, 0.f, 0.f);
    float4 a1 = a0, a2 = a0, a3 = a0;

    int e = beg;
    for (; e + 4 <= end; e += 4) {
        int   s0 = __ldg(psrc + e),     s1 = __ldg(psrc + e + 1);
        int   s2 = __ldg(psrc + e + 2), s3 = __ldg(psrc + e + 3);
        float w0 = __ldg(pw + e),       w1 = __ldg(pw + e + 1);
        float w2 = __ldg(pw + e + 2),   w3 = __ldg(pw + e + 3);
        float4 v0 = h4[(size_t)s0 * TPN + t];
        float4 v1 = h4[(size_t)s1 * TPN + t];
        float4 v2 = h4[(size_t)s2 * TPN + t];
        float4 v3 = h4[(size_t)s3 * TPN + t];
        a0.x = fmaf(v0.x, w0, a0.x); a0.y = fmaf(v0.y, w0, a0.y);
        a0.z = fmaf(v0.z, w0, a0.z); a0.w = fmaf(v0.w, w0, a0.w);
        a1.x = fmaf(v1.x, w1, a1.x); a1.y = fmaf(v1.y, w1, a1.y);
        a1.z = fmaf(v1.z, w1, a1.z); a1.w = fmaf(v1.w, w1, a1.w);
        a2.x = fmaf(v2.x, w2, a2.x); a2.y = fmaf(v2.y, w2, a2.y);
        a2.z = fmaf(v2.z, w2, a2.z); a2.w = fmaf(v2.w, w2, a2.w);
        a3.x = fmaf(v3.x, w3, a3.x); a3.y = fmaf(v3.y, w3, a3.y);
        a3.z = fmaf(v3.z, w3, a3.z); a3.w = fmaf(v3.w, w3, a3.w);
    }
    for (; e < end; e++) {
        int s   = __ldg(psrc + e);
        float w = __ldg(pw + e);
        float4 v = h4[(size_t)s * TPN + t];
        a0.x = fmaf(v.x, w, a0.x); a0.y = fmaf(v.y, w, a0.y);
        a0.z = fmaf(v.z, w, a0.z); a0.w = fmaf(v.w, w, a0.w);
    }
    float4 acc;
    acc.x = (a0.x + a1.x) + (a2.x + a3.x);
    acc.y = (a0.y + a1.y) + (a2.y + a3.y);
    acc.z = (a0.z + a1.z) + (a2.z + a3.z);
    acc.w = (a0.w + a1.w) + (a2.w + a3.w);

    float di = dinv[node];
    float s2 = di * di;
    float4 hv = h4[(size_t)node * TPN + t];
    float4 bv = reinterpret_cast<const float4*>(bias)[t];
    float4 o;
    o.x = acc.x + hv.x * s2 + bv.x;
    o.y = acc.y + hv.y * s2 + bv.y;
    o.z = acc.z + hv.z * s2 + bv.z;
    o.w = acc.w + hv.w * s2 + bv.w;
    if (RELU) {
        o.x = fmaxf(o.x, 0.f); o.y = fmaxf(o.y, 0.f);
        o.z = fmaxf(o.z, 0.f); o.w = fmaxf(o.w, 0.f);
    }
    reinterpret_cast<float4*>(out)[(size_t)node * TPN + t] = o;
}

// ---------------------------------------------------------------------------
// In-place log_softmax over rows of 64. One warp per row.
// ---------------------------------------------------------------------------
__global__ void k_logsoftmax64(float* __restrict__ out, int n)
{
    int warp = (blockIdx.x * blockDim.x + threadIdx.x) >> 5;
    int lane = threadIdx.x & 31;
    if (warp >= n) return;
    float* row = out + (size_t)warp * 64;
    float v0 = row[lane];
    float v1 = row[lane + 32];
    float m = fmaxf(v0, v1);
    #pragma unroll
    for (int o = 16; o; o >>= 1) m = fmaxf(m, __shfl_xor_sync(0xFFFFFFFFu, m, o));
    float sum = expf(v0 - m) + expf(v1 - m);
    #pragma unroll
    for (int o = 16; o; o >>= 1) sum += __shfl_xor_sync(0xFFFFFFFFu, sum, o);
    float lg = m + logf(sum);
    row[lane]      = v0 - lg;
    row[lane + 32] = v1 - lg;
}

// ---------------------------------------------------------------------------
// Launch
// ---------------------------------------------------------------------------
extern "C" void kernel_launch(void* const* d_in, const int* in_sizes, int n_in,
                              void* d_out, int out_size)
{
    const float* x  = (const float*)d_in[0];
    const void*  ei = d_in[1];
    const float* W1 = (const float*)d_in[2];
    const float* b1 = (const float*)d_in[3];
    const float* W2 = (const float*)d_in[4];
    const float* b2 = (const float*)d_in[5];
    float* out = (float*)d_out;

    const int n = NODES;
    const int E = in_sizes[1] / 2;

    int *src, *dst, *cnt, *cur, *rs, *psrc;
    float *pw, *dinv, *h1, *out1, *h2;
    __nv_bfloat16 *xhi, *xlo, *wthi, *wtlo;
    cudaGetSymbolAddress((void**)&src,  g_src);
    cudaGetSymbolAddress((void**)&dst,  g_dst);
    cudaGetSymbolAddress((void**)&cnt,  g_cnt);
    cudaGetSymbolAddress((void**)&cur,  g_cur);
    cudaGetSymbolAddress((void**)&rs,   g_rs);
    cudaGetSymbolAddress((void**)&psrc, g_psrc);
    cudaGetSymbolAddress((void**)&pw,   g_pw);
    cudaGetSymbolAddress((void**)&dinv, g_dinv);
    cudaGetSymbolAddress((void**)&h1,   g_h1);
    cudaGetSymbolAddress((void**)&out1, g_out1);
    cudaGetSymbolAddress((void**)&h2,   g_h2);
    cudaGetSymbolAddress((void**)&xhi,  g_xhi);
    cudaGetSymbolAddress((void**)&xlo,  g_xlo);
    cudaGetSymbolAddress((void**)&wthi, g_wthi);
    cudaGetSymbolAddress((void**)&wtlo, g_wtlo);

    static int smem_set = 0;
    if (!smem_set) {
        cudaFuncSetAttribute(k_gemm1_mma, cudaFuncAttributeMaxDynamicSharedMemorySize,
                             G1_SMEM);
        smem_set = 1;
    }

    // 0) detect dtype; zero counters; fused convert+count; splits
    k_detect<<<1, 1024>>>(ei, E, n);
    k_zero2 <<<(n + 255) / 256, 256>>>(cnt, cur, n);
    k_convert_count<<<(E + 255) / 256, 256>>>(ei, E, cnt);
    k_split_x <<<(n * (IN_C / 4) + 255) / 256, 256>>>(x, xhi, xlo, n * (IN_C / 4));
    k_split_wt<<<(HID_C * IN_C + 255) / 256, 256>>>(W1, wthi, wtlo);

    // 1) dinv, scan, fill
    k_dinv<<<(n + 255) / 256, 256>>>(cnt, dinv, n);
    k_scan<<<1, 1024>>>(cnt, rs, n);
    k_fill<<<(E + 255) / 256, 256>>>(src, dst, rs, cur, dinv, psrc, pw, E);

    // 2) h1 = x @ W1 via mma.sync bf16-split
    {
        dim3 grid(HID_C / 128, (n + 127) / 128);
        k_gemm1_mma<<<grid, 256, G1_SMEM>>>(xhi, xlo, wthi, wtlo, h1, n);
    }

    // 3) out1 = relu(agg(h1) + b1)
    k_agg<HID_C, true><<<(n + 3) / 4, 256>>>(rs, psrc, pw, h1, dinv, b1, out1, n);

    // 4) h2 = out1 @ W2
    {
        dim3 grid(OUT_C / 64, (n + 127) / 128);
        k_gemm_db<128, 64, 16, 8, 4><<<grid, 256>>>(out1, W2, h2, n, OUT_C, HID_C);
    }

    // 5) d_out = agg(h2) + b2
    k_agg<OUT_C, false><<<(n + 15) / 16, 256>>>(rs, psrc, pw, h2, dinv, b2, out, n);

    // 6) log_softmax in place
    k_logsoftmax64<<<(n * 32 + 255) / 256, 256>>>(out, n);
}

// round 9
// speedup vs baseline: 1.0701x; 1.0701x over previous
#include <cuda_runtime.h>
#include <cuda_bf16.h>
#include <math.h>
#include <stdint.h>

// ---------------------------------------------------------------------------
// GCN_47760036331636: 2-layer GCN.
//   Layer1 GEMM via mma.sync bf16-split; CSR-gather aggregation;
//   SIMT cp.async GEMM2; log_softmax fused into layer-2 aggregation.
// ---------------------------------------------------------------------------

#define NODES  50000
#define EDGES  800000
#define IN_C   512
#define HID_C  256
#define OUT_C  64

__device__ int   g_is64;
__device__ int   g_src [EDGES];
__device__ int   g_dst [EDGES];
__device__ int   g_cnt [NODES];
__device__ int   g_cur [NODES];
__device__ int   g_rs  [NODES + 4];
__device__ int   g_psrc[EDGES];
__device__ float g_pw  [EDGES];
__device__ float g_dinv[NODES];
__device__ __nv_bfloat16 g_xhi [(size_t)NODES * IN_C];
__device__ __nv_bfloat16 g_xlo [(size_t)NODES * IN_C];
__device__ __nv_bfloat16 g_wthi[(size_t)HID_C * IN_C];
__device__ __nv_bfloat16 g_wtlo[(size_t)HID_C * IN_C];
__device__ float g_h1  [(size_t)NODES * HID_C];
__device__ float g_out1[(size_t)NODES * HID_C];
__device__ float g_h2  [(size_t)NODES * OUT_C];

#define CP_ASYNC16(dst32, srcp, pbytes) \
    asm volatile("cp.async.cg.shared.global [%0], [%1], 16, %2;" \
                 :: "r"(dst32), "l"(srcp), "r"(pbytes) : "memory")
#define CP_COMMIT()  asm volatile("cp.async.commit_group;" ::: "memory")
#define CP_WAIT(N)   asm volatile("cp.async.wait_group %0;" :: "n"(N) : "memory")

// ---------------------------------------------------------------------------
// Splits (launched FIRST so gemm1 can be launch #4 for ncu capture)
// ---------------------------------------------------------------------------
__global__ void k_split_x(const float* __restrict__ x, __nv_bfloat16* __restrict__ hi,
                          __nv_bfloat16* __restrict__ lo, int total4)
{
    int i = blockIdx.x * blockDim.x + threadIdx.x;
    if (i >= total4) return;
    float4 v = reinterpret_cast<const float4*>(x)[i];
    __nv_bfloat16 h0 = __float2bfloat16(v.x), h1 = __float2bfloat16(v.y);
    __nv_bfloat16 h2 = __float2bfloat16(v.z), h3 = __float2bfloat16(v.w);
    __nv_bfloat16 l0 = __float2bfloat16(v.x - __bfloat162float(h0));
    __nv_bfloat16 l1 = __float2bfloat16(v.y - __bfloat162float(h1));
    __nv_bfloat16 l2 = __float2bfloat16(v.z - __bfloat162float(h2));
    __nv_bfloat16 l3 = __float2bfloat16(v.w - __bfloat162float(h3));
    reinterpret_cast<__nv_bfloat162*>(hi)[i * 2 + 0] = __nv_bfloat162(h0, h1);
    reinterpret_cast<__nv_bfloat162*>(hi)[i * 2 + 1] = __nv_bfloat162(h2, h3);
    reinterpret_cast<__nv_bfloat162*>(lo)[i * 2 + 0] = __nv_bfloat162(l0, l1);
    reinterpret_cast<__nv_bfloat162*>(lo)[i * 2 + 1] = __nv_bfloat162(l2, l3);
}

__global__ void k_split_wt(const float* __restrict__ W, __nv_bfloat16* __restrict__ hi,
                           __nv_bfloat16* __restrict__ lo)
{
    int idx = blockIdx.x * blockDim.x + threadIdx.x;
    if (idx >= HID_C * IN_C) return;
    int k = idx / HID_C, n = idx % HID_C;
    float v = W[idx];
    __nv_bfloat16 h = __float2bfloat16(v);
    hi[(size_t)n * IN_C + k] = h;
    lo[(size_t)n * IN_C + k] = __float2bfloat16(v - __bfloat162float(h));
}

__global__ void k_detect(const void* ei, int E, int n) {
    int cnt = E < 1024 ? E : 1024;
    int bad = 0;
    if ((int)threadIdx.x < cnt) {
        unsigned long long v = ((const unsigned long long*)ei)[threadIdx.x];
        bad = (v >= (unsigned long long)n);
    }
    bad = __syncthreads_or(bad);
    if (threadIdx.x == 0) g_is64 = !bad;
}

// ---------------------------------------------------------------------------
// mma.sync bf16-split GEMM1 (launch slot 4 -> gets ncu-profiled)
// ---------------------------------------------------------------------------
#define G1_BK     32
#define G1_SA     40
#define G1_TILE   (128 * G1_SA)
#define G1_SMEM   (8 * G1_TILE * 2)       // 81920 bytes

__device__ __forceinline__ uint32_t ld2h(const __nv_bfloat16* base, int row, int col) {
    return *reinterpret_cast<const uint32_t*>(base + row * G1_SA + col);
}
__device__ __forceinline__ void mma_bf16(float* d, const uint32_t* a, const uint32_t* b) {
    asm volatile(
        "mma.sync.aligned.m16n8k16.row.col.f32.bf16.bf16.f32 "
        "{%0,%1,%2,%3}, {%4,%5,%6,%7}, {%8,%9}, {%0,%1,%2,%3};"
        : "+f"(d[0]), "+f"(d[1]), "+f"(d[2]), "+f"(d[3])
        : "r"(a[0]), "r"(a[1]), "r"(a[2]), "r"(a[3]), "r"(b[0]), "r"(b[1]));
}

__global__ void __launch_bounds__(256) k_gemm1_mma(
    const __nv_bfloat16* __restrict__ xhi, const __nv_bfloat16* __restrict__ xlo,
    const __nv_bfloat16* __restrict__ wthi, const __nv_bfloat16* __restrict__ wtlo,
    float* __restrict__ C, int M)
{
    extern __shared__ __nv_bfloat16 sm[];
    __nv_bfloat16* AHI[2] = { sm,              sm + G1_TILE     };
    __nv_bfloat16* ALO[2] = { sm + 2*G1_TILE,  sm + 3*G1_TILE   };
    __nv_bfloat16* BHI[2] = { sm + 4*G1_TILE,  sm + 5*G1_TILE   };
    __nv_bfloat16* BLO[2] = { sm + 6*G1_TILE,  sm + 7*G1_TILE   };

    const int tid  = threadIdx.x;
    const int warp = tid >> 5, lane = tid & 31;
    const int qr = lane >> 2, qc = lane & 3;
    const int wm0 = (warp >> 2) * 64;
    const int wn0 = (warp & 3) * 32;
    const int mBase   = blockIdx.y * 128;
    const int colBase = blockIdx.x * 128;

    auto load_stage = [&](int buf, int k0) {
        #pragma unroll
        for (int l = 0; l < 2; l++) {
            int idx = tid + l * 256;
            int r = idx >> 2, ch = idx & 3;
            uint32_t soff = (uint32_t)((r * G1_SA + ch * 8) * 2);
            int gm  = mBase + r;
            int gmc = gm < M ? gm : M - 1;
            int p   = gm < M ? 16 : 0;
            const __nv_bfloat16* sa_hi = xhi + (size_t)gmc * IN_C + k0 + ch * 8;
            const __nv_bfloat16* sa_lo = xlo + (size_t)gmc * IN_C + k0 + ch * 8;
            CP_ASYNC16((uint32_t)__cvta_generic_to_shared(AHI[buf]) + soff, sa_hi, p);
            CP_ASYNC16((uint32_t)__cvta_generic_to_shared(ALO[buf]) + soff, sa_lo, p);
            const __nv_bfloat16* sb_hi = wthi + (size_t)(colBase + r) * IN_C + k0 + ch * 8;
            const __nv_bfloat16* sb_lo = wtlo + (size_t)(colBase + r) * IN_C + k0 + ch * 8;
            CP_ASYNC16((uint32_t)__cvta_generic_to_shared(BHI[buf]) + soff, sb_hi, 16);
            CP_ASYNC16((uint32_t)__cvta_generic_to_shared(BLO[buf]) + soff, sb_lo, 16);
        }
        CP_COMMIT();
    };

    float acc[4][4][4];
    #pragma unroll
    for (int i = 0; i < 4; i++)
        #pragma unroll
        for (int j = 0; j < 4; j++)
            #pragma unroll
            for (int r = 0; r < 4; r++) acc[i][j][r] = 0.0f;

    const int nk = IN_C / G1_BK;
    load_stage(0, 0);

    for (int kt = 0; kt < nk; kt++) {
        int buf = kt & 1;
        if (kt + 1 < nk) { load_stage(buf ^ 1, (kt + 1) * G1_BK); CP_WAIT(1); }
        else             { CP_WAIT(0); }
        __syncthreads();

        #pragma unroll
        for (int ks = 0; ks < 2; ks++) {
            const int kh = ks * 16;
            uint32_t ahi[4][4], alo[4][4], bhi[4][2], blo[4][2];
            #pragma unroll
            for (int i = 0; i < 4; i++) {
                int r0 = wm0 + i * 16 + qr;
                int c0 = kh + qc * 2;
                ahi[i][0] = ld2h(AHI[buf], r0,     c0);
                ahi[i][1] = ld2h(AHI[buf], r0 + 8, c0);
                ahi[i][2] = ld2h(AHI[buf], r0,     c0 + 8);
                ahi[i][3] = ld2h(AHI[buf], r0 + 8, c0 + 8);
                alo[i][0] = ld2h(ALO[buf], r0,     c0);
                alo[i][1] = ld2h(ALO[buf], r0 + 8, c0);
                alo[i][2] = ld2h(ALO[buf], r0,     c0 + 8);
                alo[i][3] = ld2h(ALO[buf], r0 + 8, c0 + 8);
            }
            #pragma unroll
            for (int j = 0; j < 4; j++) {
                int nr = wn0 + j * 8 + qr;
                int c0 = kh + qc * 2;
                bhi[j][0] = ld2h(BHI[buf], nr, c0);
                bhi[j][1] = ld2h(BHI[buf], nr, c0 + 8);
                blo[j][0] = ld2h(BLO[buf], nr, c0);
                blo[j][1] = ld2h(BLO[buf], nr, c0 + 8);
            }
            #pragma unroll
            for (int i = 0; i < 4; i++)
                #pragma unroll
                for (int j = 0; j < 4; j++) {
                    mma_bf16(acc[i][j], ahi[i], bhi[j]);
                    mma_bf16(acc[i][j], ahi[i], blo[j]);
                    mma_bf16(acc[i][j], alo[i], bhi[j]);
                }
        }
        __syncthreads();
    }

    #pragma unroll
    for (int i = 0; i < 4; i++) {
        int m0 = mBase + wm0 + i * 16 + qr;
        #pragma unroll
        for (int j = 0; j < 4; j++) {
            int nc = colBase + wn0 + j * 8 + qc * 2;
            if (m0 < M)
                *reinterpret_cast<float2*>(C + (size_t)m0 * HID_C + nc) =
                    make_float2(acc[i][j][0], acc[i][j][1]);
            if (m0 + 8 < M)
                *reinterpret_cast<float2*>(C + (size_t)(m0 + 8) * HID_C + nc) =
                    make_float2(acc[i][j][2], acc[i][j][3]);
        }
    }
}

// ---------------------------------------------------------------------------
// Graph build
// ---------------------------------------------------------------------------
__global__ void k_zero2(int* a, int* b, int n) {
    int i = blockIdx.x * blockDim.x + threadIdx.x;
    if (i < n) { a[i] = 0; b[i] = 0; }
}

__global__ void k_convert_count(const void* ei, int E, int* cnt) {
    int e = blockIdx.x * blockDim.x + threadIdx.x;
    if (e >= E) return;
    int s, d;
    if (g_is64) {
        const long long* p = (const long long*)ei;
        s = (int)p[e]; d = (int)p[E + e];
    } else {
        const int* p = (const int*)ei;
        s = p[e]; d = p[E + e];
    }
    g_src[e] = s;
    g_dst[e] = d;
    atomicAdd(cnt + d, 1);
}

__global__ void k_dinv(const int* __restrict__ cnt, float* __restrict__ dinv, int n) {
    int i = blockIdx.x * blockDim.x + threadIdx.x;
    if (i < n) dinv[i] = rsqrtf(1.0f + (float)cnt[i]);
}

// Single-block exclusive scan, int4-vectorized: 4096 elements per chunk.
__global__ void k_scan(const int* __restrict__ cnt, int* __restrict__ rs, int n) {
    __shared__ int wsum[32];
    __shared__ int carry;
    int tid = threadIdx.x, lane = tid & 31, wid = tid >> 5;
    if (tid == 0) carry = 0;
    __syncthreads();
    int nPad = (n + 3) & ~3;
    for (int base = 0; base < nPad; base += 4096) {
        int idx = base + tid * 4;
        int4 v = make_int4(0, 0, 0, 0);
        if (idx + 3 < n)      v = *reinterpret_cast<const int4*>(cnt + idx);
        else if (idx < n) {
            v.x = cnt[idx];
            v.y = (idx + 1 < n) ? cnt[idx + 1] : 0;
            v.z = (idx + 2 < n) ? cnt[idx + 2] : 0;
        }
        int t0 = v.x, t1 = t0 + v.y, t2 = t1 + v.z, T = t2 + v.w;
        int x = T;
        #pragma unroll
        for (int o = 1; o < 32; o <<= 1) {
            int t = __shfl_up_sync(0xFFFFFFFFu, x, o);
            if (lane >= o) x += t;
        }
        if (lane == 31) wsum[wid] = x;
        __syncthreads();
        if (wid == 0) {
            int y = wsum[lane];
            #pragma unroll
            for (int o = 1; o < 32; o <<= 1) {
                int t = __shfl_up_sync(0xFFFFFFFFu, y, o);
                if (lane >= o) y += t;
            }
            wsum[lane] = y;
        }
        __syncthreads();
        int off = carry + x - T + (wid ? wsum[wid - 1] : 0);
        if (idx < n) {
            int4 o4 = make_int4(off, off + t0, off + t1, off + t2);
            *reinterpret_cast<int4*>(rs + idx) = o4;   // rs padded to n+4
        }
        int total = wsum[31];
        __syncthreads();
        if (tid == 0) carry += total;
        __syncthreads();
    }
    if (tid == 0) rs[n] = carry;
}

__global__ void k_fill(const int* __restrict__ src, const int* __restrict__ dst,
                       const int* __restrict__ rs, int* __restrict__ cur,
                       const float* __restrict__ dinv,
                       int* __restrict__ psrc, float* __restrict__ pw, int E)
{
    int e = blockIdx.x * blockDim.x + threadIdx.x;
    if (e >= E) return;
    int s = src[e], d = dst[e];
    int pos = rs[d] + atomicAdd(cur + d, 1);
    psrc[pos] = s;
    pw[pos]   = dinv[s] * dinv[d];
}

// ---------------------------------------------------------------------------
// Double-buffered cp.async fp32 GEMM (layer 2)
// ---------------------------------------------------------------------------
template<int BM, int BN, int BK, int TM, int TN>
__global__ void k_gemm_db(const float* __restrict__ A, const float* __restrict__ B,
                          float* __restrict__ C, int M, int N, int K)
{
    constexpr int THREADS = (BM / TM) * (BN / TN);
    constexpr int APAD = 4;
    __shared__ float As[2][BM][BK + APAD];
    __shared__ float Bs[2][BK][BN];

    const int tid = threadIdx.x;
    const int tx  = tid % (BN / TN);
    const int ty  = tid / (BN / TN);
    const int rowBase = blockIdx.y * BM;
    const int colBase = blockIdx.x * BN;

    constexpr int NA = BM * BK / 4 / THREADS;
    constexpr int NB = BK * BN / 4 / THREADS;

    int a_ar[NA], a_ac[NA];
    #pragma unroll
    for (int l = 0; l < NA; l++) {
        int idx = tid + l * THREADS;
        a_ar[l] = idx / (BK / 4);
        a_ac[l] = (idx % (BK / 4)) * 4;
    }
    int b_br[NB], b_bc[NB];
    #pragma unroll
    for (int l = 0; l < NB; l++) {
        int idx = tid + l * THREADS;
        b_br[l] = idx / (BN / 4);
        b_bc[l] = (idx % (BN / 4)) * 4;
    }

    auto load_tiles = [&](int buf, int k0) {
        #pragma unroll
        for (int l = 0; l < NA; l++) {
            int gr = rowBase + a_ar[l];
            int grc = gr < M ? gr : M - 1;
            const float* src = A + (size_t)grc * K + k0 + a_ac[l];
            uint32_t d = (uint32_t)__cvta_generic_to_shared(&As[buf][a_ar[l]][a_ac[l]]);
            int p = gr < M ? 16 : 0;
            CP_ASYNC16(d, src, p);
        }
        #pragma unroll
        for (int l = 0; l < NB; l++) {
            const float* src = B + (size_t)(k0 + b_br[l]) * N + colBase + b_bc[l];
            uint32_t d = (uint32_t)__cvta_generic_to_shared(&Bs[buf][b_br[l]][b_bc[l]]);
            CP_ASYNC16(d, src, 16);
        }
        CP_COMMIT();
    };

    float acc[TM][TN];
    #pragma unroll
    for (int i = 0; i < TM; i++)
        #pragma unroll
        for (int j = 0; j < TN; j++) acc[i][j] = 0.0f;

    const int nk = K / BK;
    load_tiles(0, 0);

    for (int kt = 0; kt < nk; kt++) {
        int buf = kt & 1;
        if (kt + 1 < nk) { load_tiles(buf ^ 1, (kt + 1) * BK); CP_WAIT(1); }
        else             { CP_WAIT(0); }
        __syncthreads();

        #pragma unroll
        for (int kk = 0; kk < BK; kk++) {
            float a[TM], b[TN];
            #pragma unroll
            for (int i = 0; i < TM; i++) a[i] = As[buf][ty * TM + i][kk];
            #pragma unroll
            for (int j = 0; j < TN; j += 4) {
                float4 t = *reinterpret_cast<const float4*>(&Bs[buf][kk][tx * TN + j]);
                b[j] = t.x; b[j + 1] = t.y; b[j + 2] = t.z; b[j + 3] = t.w;
            }
            #pragma unroll
            for (int i = 0; i < TM; i++)
                #pragma unroll
                for (int j = 0; j < TN; j++)
                    acc[i][j] = fmaf(a[i], b[j], acc[i][j]);
        }
        __syncthreads();
    }

    #pragma unroll
    for (int i = 0; i < TM; i++) {
        int gr = rowBase + ty * TM + i;
        if (gr >= M) continue;
        #pragma unroll
        for (int j = 0; j < TN; j += 4) {
            float4 v = make_float4(acc[i][j], acc[i][j+1], acc[i][j+2], acc[i][j+3]);
            *reinterpret_cast<float4*>(&C[(size_t)gr * N + colBase + tx * TN + j]) = v;
        }
    }
}

// ---------------------------------------------------------------------------
// Layer-1 CSR aggregation (unrolled x4), + self-loop + bias + relu
// ---------------------------------------------------------------------------
template<int C, bool RELU>
__global__ void k_agg(const int* __restrict__ rs, const int* __restrict__ psrc,
                      const float* __restrict__ pw, const float* __restrict__ h,
                      const float* __restrict__ dinv, const float* __restrict__ bias,
                      float* __restrict__ out, int n)
{
    constexpr int TPN = C / 4;
    constexpr int NPB = 256 / TPN;
    int sub  = threadIdx.x / TPN;
    int t    = threadIdx.x % TPN;
    int node = blockIdx.x * NPB + sub;
    if (node >= n) return;

    const float4* h4 = reinterpret_cast<const float4*>(h);
    int beg = rs[node], end = rs[node + 1];

    float4 a0 = make_float4(0.f, 0.f, 0.f, 0.f);
    float4 a1 = a0, a2 = a0, a3 = a0;

    int e = beg;
    for (; e + 4 <= end; e += 4) {
        int   s0 = __ldg(psrc + e),     s1 = __ldg(psrc + e + 1);
        int   s2 = __ldg(psrc + e + 2), s3 = __ldg(psrc + e + 3);
        float w0 = __ldg(pw + e),       w1 = __ldg(pw + e + 1);
        float w2 = __ldg(pw + e + 2),   w3 = __ldg(pw + e + 3);
        float4 v0 = h4[(size_t)s0 * TPN + t];
        float4 v1 = h4[(size_t)s1 * TPN + t];
        float4 v2 = h4[(size_t)s2 * TPN + t];
        float4 v3 = h4[(size_t)s3 * TPN + t];
        a0.x = fmaf(v0.x, w0, a0.x); a0.y = fmaf(v0.y, w0, a0.y);
        a0.z = fmaf(v0.z, w0, a0.z); a0.w = fmaf(v0.w, w0, a0.w);
        a1.x = fmaf(v1.x, w1, a1.x); a1.y = fmaf(v1.y, w1, a1.y);
        a1.z = fmaf(v1.z, w1, a1.z); a1.w = fmaf(v1.w, w1, a1.w);
        a2.x = fmaf(v2.x, w2, a2.x); a2.y = fmaf(v2.y, w2, a2.y);
        a2.z = fmaf(v2.z, w2, a2.z); a2.w = fmaf(v2.w, w2, a2.w);
        a3.x = fmaf(v3.x, w3, a3.x); a3.y = fmaf(v3.y, w3, a3.y);
        a3.z = fmaf(v3.z, w3, a3.z); a3.w = fmaf(v3.w, w3, a3.w);
    }
    for (; e < end; e++) {
        int s   = __ldg(psrc + e);
        float w = __ldg(pw + e);
        float4 v = h4[(size_t)s * TPN + t];
        a0.x = fmaf(v.x, w, a0.x); a0.y = fmaf(v.y, w, a0.y);
        a0.z = fmaf(v.z, w, a0.z); a0.w = fmaf(v.w, w, a0.w);
    }
    float4 acc;
    acc.x = (a0.x + a1.x) + (a2.x + a3.x);
    acc.y = (a0.y + a1.y) + (a2.y + a3.y);
    acc.z = (a0.z + a1.z) + (a2.z + a3.z);
    acc.w = (a0.w + a1.w) + (a2.w + a3.w);

    float di = dinv[node];
    float s2 = di * di;
    float4 hv = h4[(size_t)node * TPN + t];
    float4 bv = reinterpret_cast<const float4*>(bias)[t];
    float4 o;
    o.x = acc.x + hv.x * s2 + bv.x;
    o.y = acc.y + hv.y * s2 + bv.y;
    o.z = acc.z + hv.z * s2 + bv.z;
    o.w = acc.w + hv.w * s2 + bv.w;
    if (RELU) {
        o.x = fmaxf(o.x, 0.f); o.y = fmaxf(o.y, 0.f);
        o.z = fmaxf(o.z, 0.f); o.w = fmaxf(o.w, 0.f);
    }
    reinterpret_cast<float4*>(out)[(size_t)node * TPN + t] = o;
}

// ---------------------------------------------------------------------------
// Layer-2 aggregation (C=64) with fused log_softmax.
// 16 threads/node; shfl reduction over the 16-lane group (masks 1,2,4,8).
// ---------------------------------------------------------------------------
__global__ void k_agg2_lsm(const int* __restrict__ rs, const int* __restrict__ psrc,
                           const float* __restrict__ pw, const float* __restrict__ h,
                           const float* __restrict__ dinv, const float* __restrict__ bias,
                           float* __restrict__ out, int n)
{
    constexpr int TPN = OUT_C / 4;   // 16
    constexpr int NPB = 256 / TPN;   // 16
    int sub  = threadIdx.x / TPN;
    int t    = threadIdx.x % TPN;
    int node = blockIdx.x * NPB + sub;
    if (node >= n) return;

    const float4* h4 = reinterpret_cast<const float4*>(h);
    int beg = rs[node], end = rs[node + 1];

    float4 a0 = make_float4(0.f, 0.f, 0.f, 0.f);
    float4 a1 = a0, a2 = a0, a3 = a0;
    int e = beg;
    for (; e + 4 <= end; e += 4) {
        int   s0 = __ldg(psrc + e),     s1 = __ldg(psrc + e + 1);
        int   s2 = __ldg(psrc + e + 2), s3 = __ldg(psrc + e + 3);
        float w0 = __ldg(pw + e),       w1 = __ldg(pw + e + 1);
        float w2 = __ldg(pw + e + 2),   w3 = __ldg(pw + e + 3);
        float4 v0 = h4[(size_t)s0 * TPN + t];
        float4 v1 = h4[(size_t)s1 * TPN + t];
        float4 v2 = h4[(size_t)s2 * TPN + t];
        float4 v3 = h4[(size_t)s3 * TPN + t];
        a0.x = fmaf(v0.x, w0, a0.x); a0.y = fmaf(v0.y, w0, a0.y);
        a0.z = fmaf(v0.z, w0, a0.z); a0.w = fmaf(v0.w, w0, a0.w);
        a1.x = fmaf(v1.x, w1, a1.x); a1.y = fmaf(v1.y, w1, a1.y);
        a1.z = fmaf(v1.z, w1, a1.z); a1.w = fmaf(v1.w, w1, a1.w);
        a2.x = fmaf(v2.x, w2, a2.x); a2.y = fmaf(v2.y, w2, a2.y);
        a2.z = fmaf(v2.z, w2, a2.z); a2.w = fmaf(v2.w, w2, a2.w);
        a3.x = fmaf(v3.x, w3, a3.x); a3.y = fmaf(v3.y, w3, a3.y);
        a3.z = fmaf(v3.z, w3, a3.z); a3.w = fmaf(v3.w, w3, a3.w);
    }
    for (; e < end; e++) {
        int s   = __ldg(psrc + e);
        float w = __ldg(pw + e);
        float4 v = h4[(size_t)s * TPN + t];
        a0.x = fmaf(v.x, w, a0.x); a0.y = fmaf(v.y, w, a0.y);
        a0.z = fmaf(v.z, w, a0.z); a0.w = fmaf(v.w, w, a0.w);
    }
    float di = dinv[node];
    float s2 = di * di;
    float4 hv = h4[(size_t)node * TPN + t];
    float4 bv = reinterpret_cast<const float4*>(bias)[t];
    float4 o;
    o.x = (a0.x + a1.x) + (a2.x + a3.x) + hv.x * s2 + bv.x;
    o.y = (a0.y + a1.y) + (a2.y + a3.y) + hv.y * s2 + bv.y;
    o.z = (a0.z + a1.z) + (a2.z + a3.z) + hv.z * s2 + bv.z;
    o.w = (a0.w + a1.w) + (a2.w + a3.w) + hv.w * s2 + bv.w;

    // fused log_softmax over the node's 64 values (16 lanes x 4)
    float m = fmaxf(fmaxf(o.x, o.y), fmaxf(o.z, o.w));
    #pragma unroll
    for (int off = 1; off < TPN; off <<= 1)
        m = fmaxf(m, __shfl_xor_sync(0xFFFFFFFFu, m, off));
    float s = expf(o.x - m) + expf(o.y - m) + expf(o.z - m) + expf(o.w - m);
    #pragma unroll
    for (int off = 1; off < TPN; off <<= 1)
        s += __shfl_xor_sync(0xFFFFFFFFu, s, off);
    float lg = m + logf(s);
    o.x -= lg; o.y -= lg; o.z -= lg; o.w -= lg;
    reinterpret_cast<float4*>(out)[(size_t)node * TPN + t] = o;
}

// ---------------------------------------------------------------------------
// Launch
// ---------------------------------------------------------------------------
extern "C" void kernel_launch(void* const* d_in, const int* in_sizes, int n_in,
                              void* d_out, int out_size)
{
    const float* x  = (const float*)d_in[0];
    const void*  ei = d_in[1];
    const float* W1 = (const float*)d_in[2];
    const float* b1 = (const float*)d_in[3];
    const float* W2 = (const float*)d_in[4];
    const float* b2 = (const float*)d_in[5];
    float* out = (float*)d_out;

    const int n = NODES;
    const int E = in_sizes[1] / 2;

    int *src, *dst, *cnt, *cur, *rs, *psrc;
    float *pw, *dinv, *h1, *out1, *h2;
    __nv_bfloat16 *xhi, *xlo, *wthi, *wtlo;
    cudaGetSymbolAddress((void**)&src,  g_src);
    cudaGetSymbolAddress((void**)&dst,  g_dst);
    cudaGetSymbolAddress((void**)&cnt,  g_cnt);
    cudaGetSymbolAddress((void**)&cur,  g_cur);
    cudaGetSymbolAddress((void**)&rs,   g_rs);
    cudaGetSymbolAddress((void**)&psrc, g_psrc);
    cudaGetSymbolAddress((void**)&pw,   g_pw);
    cudaGetSymbolAddress((void**)&dinv, g_dinv);
    cudaGetSymbolAddress((void**)&h1,   g_h1);
    cudaGetSymbolAddress((void**)&out1, g_out1);
    cudaGetSymbolAddress((void**)&h2,   g_h2);
    cudaGetSymbolAddress((void**)&xhi,  g_xhi);
    cudaGetSymbolAddress((void**)&xlo,  g_xlo);
    cudaGetSymbolAddress((void**)&wthi, g_wthi);
    cudaGetSymbolAddress((void**)&wtlo, g_wtlo);

    static int smem_set = 0;
    if (!smem_set) {
        cudaFuncSetAttribute(k_gemm1_mma, cudaFuncAttributeMaxDynamicSharedMemorySize,
                             G1_SMEM);
        smem_set = 1;
    }

    // Launches 1-3: splits + detect (gemm1 must be launch #4 for ncu capture)
    k_split_x <<<(n * (IN_C / 4) + 255) / 256, 256>>>(x, xhi, xlo, n * (IN_C / 4));
    k_split_wt<<<(HID_C * IN_C + 255) / 256, 256>>>(W1, wthi, wtlo);
    k_detect<<<1, 1024>>>(ei, E, n);

    // Launch 4: h1 = x @ W1
    {
        dim3 grid(HID_C / 128, (n + 127) / 128);
        k_gemm1_mma<<<grid, 256, G1_SMEM>>>(xhi, xlo, wthi, wtlo, h1, n);
    }

    // Graph build (overlap-agnostic; stream-ordered after gemm1)
    k_zero2<<<(n + 255) / 256, 256>>>(cnt, cur, n);
    k_convert_count<<<(E + 255) / 256, 256>>>(ei, E, cnt);
    k_dinv<<<(n + 255) / 256, 256>>>(cnt, dinv, n);
    k_scan<<<1, 1024>>>(cnt, rs, n);
    k_fill<<<(E + 255) / 256, 256>>>(src, dst, rs, cur, dinv, psrc, pw, E);

    // out1 = relu(agg(h1) + b1)
    k_agg<HID_C, true><<<(n + 3) / 4, 256>>>(rs, psrc, pw, h1, dinv, b1, out1, n);

    // h2 = out1 @ W2
    {
        dim3 grid(OUT_C / 64, (n + 127) / 128);
        k_gemm_db<128, 64, 16, 8, 4><<<grid, 256>>>(out1, W2, h2, n, OUT_C, HID_C);
    }

    // d_out = log_softmax(agg(h2) + b2)   (fused)
    k_agg2_lsm<<<(n + 15) / 16, 256>>>(rs, psrc, pw, h2, dinv, b2, out, n);
}